// round 9
// baseline (speedup 1.0000x reference)
#include <cuda_runtime.h>
#include <cstdint>

#define BB 32
#define TT 2048
#define CC 1152
#define OO 29
#define NCHUNK 16
#define NBLK (BB * NCHUNK)    // 512 blocks
#define TROWS (TT / NCHUNK)   // 128 t-rows per chunk
#define C4 (CC / 4)           // 288 float4 per row

// Raw per-(b,chunk) column sums. Fully overwritten every launch before any
// finisher reads them -> deterministic under graph replay.
__device__ float    g_partial[BB * NCHUNK * CC];
// Per-batch completion counters; each batch's finisher resets its own slot,
// so every graph replay starts from zero.
__device__ unsigned g_cnt[BB];

// ---------------------------------------------------------------------------
// Single kernel, 512 blocks x 288 threads, one flat wave (regs held lean).
//
//   (a) stream x, reduce 128 t-rows per (b,chunk). 288 x 16B = one 4608B row
//       -> perfectly coalesced. This phase measured 6.4 TB/s in round 2.
//   (b) store raw column sums (float4, coalesced) -> g_partial.
//   (c) LAST block of each batch (per-batch atomic counter) collapses the 16
//       chunk vectors in smem, projects ONCE against the 29 W rows, applies
//       bias and 1/length, writes out[b].
//
// Why: round 8 showed the per-(b,chunk) projection tail re-read W 512 times
// (68 MB of L2 traffic, ~9.6 us of near-zero-DRAM tail). Collapsing first
// cuts W traffic to 32 x 133 KB = 4.3 MB; the ordered collapse loop keeps
// the output bitwise deterministic.
// ---------------------------------------------------------------------------
__global__ __launch_bounds__(C4, 4) void fused_kernel(const float* __restrict__ x,
                                                      const int*   __restrict__ length,
                                                      const float* __restrict__ W,
                                                      const float* __restrict__ bias,
                                                      float*       __restrict__ out) {
    __shared__ float s[CC];        // collapsed batch column sums (finisher)
    __shared__ float zdot[32];     // per-output dots (finisher)
    __shared__ bool  is_last;

    const int blk   = blockIdx.x;
    const int b     = blk / NCHUNK;
    const int chunk = blk % NCHUNK;
    const int tid   = threadIdx.x;

    // ---- (a) T-reduction mainloop (round-2 config: unroll 4, plain LDG) ----
    const float4* xp = reinterpret_cast<const float4*>(x)
                     + ((size_t)b * TT + (size_t)chunk * TROWS) * C4 + tid;

    float4 acc = make_float4(0.f, 0.f, 0.f, 0.f);

    #pragma unroll 1
    for (int t = 0; t < TROWS; t += 4) {
        float4 v0 = xp[(size_t)(t + 0) * C4];
        float4 v1 = xp[(size_t)(t + 1) * C4];
        float4 v2 = xp[(size_t)(t + 2) * C4];
        float4 v3 = xp[(size_t)(t + 3) * C4];
        acc.x += (v0.x + v1.x) + (v2.x + v3.x);
        acc.y += (v0.y + v1.y) + (v2.y + v3.y);
        acc.z += (v0.z + v1.z) + (v2.z + v3.z);
        acc.w += (v0.w + v1.w) + (v2.w + v3.w);
    }

    // ---- (b) publish raw chunk sums ----
    reinterpret_cast<float4*>(g_partial)[(size_t)blk * C4 + tid] = acc;

    __syncthreads();                 // all stores for this block issued
    if (tid == 0) {
        __threadfence();             // release: publish sums before counting
        unsigned old = atomicAdd(&g_cnt[b], 1u);
        is_last = (old == NCHUNK - 1);
    }
    __syncthreads();
    if (!is_last) return;

    // ---- (c) per-batch finisher ----
    __threadfence();                 // acquire: see all 16 chunk vectors

    // Collapse 16 chunk vectors -> s (ordered loop => deterministic).
    {
        const float4* gp4 = reinterpret_cast<const float4*>(g_partial)
                          + (size_t)b * NCHUNK * C4 + tid;
        float4 v = gp4[0];
        #pragma unroll
        for (int ch = 1; ch < NCHUNK; ch++) {
            float4 p = gp4[(size_t)ch * C4];
            v.x += p.x; v.y += p.y; v.z += p.z; v.w += p.w;
        }
        reinterpret_cast<float4*>(s)[tid] = v;
    }
    __syncthreads();

    // Project: 9 warps round-robin 29 outputs. val[c] = s[c]/64 - 2*TT.
    const int warp = tid >> 5;
    const int lane = tid & 31;
    const float inv64 = 1.0f / 64.0f;
    const float shift = 2.0f * (float)TT;    // full-batch shift: 4096

    const float4* s4 = reinterpret_cast<const float4*>(s);

    for (int o = warp; o < OO; o += 9) {
        const float4* wr4 = reinterpret_cast<const float4*>(W + (size_t)o * CC);
        float dot = 0.f;
        #pragma unroll
        for (int k = 0; k < C4 / 32; k++) {       // 9 iterations
            int idx = lane + k * 32;
            float4 w = wr4[idx];
            float4 v = s4[idx];
            dot = fmaf(fmaf(v.x, inv64, -shift), w.x, dot);
            dot = fmaf(fmaf(v.y, inv64, -shift), w.y, dot);
            dot = fmaf(fmaf(v.z, inv64, -shift), w.z, dot);
            dot = fmaf(fmaf(v.w, inv64, -shift), w.w, dot);
        }
        #pragma unroll
        for (int off = 16; off; off >>= 1)
            dot += __shfl_down_sync(0xffffffffu, dot, off);
        if (lane == 0)
            zdot[o] = dot;
    }
    __syncthreads();

    if (tid < OO)
        out[(size_t)b * OO + tid] = (zdot[tid] + (float)TT * bias[tid])
                                  / (float)length[b];
    if (tid == 0)
        g_cnt[b] = 0u;               // reset for next graph replay
}

// ---------------------------------------------------------------------------
// Inputs (metadata order): x f32 [B,T,C], length i32 [B], W f32 [O,C], b f32 [O]
// Output: f32 [B,O]
// NOTE: length is int32 on device (JAX downcasts int64 with x64 off).
// ---------------------------------------------------------------------------
extern "C" void kernel_launch(void* const* d_in, const int* in_sizes, int n_in,
                              void* d_out, int out_size) {
    (void)in_sizes; (void)n_in; (void)out_size;
    const float* x      = (const float*)d_in[0];
    const int*   length = (const int*)d_in[1];
    const float* W      = (const float*)d_in[2];
    const float* bias   = (const float*)d_in[3];
    float*       out    = (float*)d_out;

    fused_kernel<<<NBLK, C4>>>(x, length, W, bias, out);
}

// round 13
// speedup vs baseline: 1.0111x; 1.0111x over previous
#include <cuda_runtime.h>
#include <cstdint>

#define BB 32
#define TT 2048
#define CC 1152
#define OO 29
#define NCHUNK 16
#define NBLK (BB * NCHUNK)    // 512 blocks
#define TROWS (TT / NCHUNK)   // 128 t-rows per chunk
#define C4 (CC / 4)           // 288 float4 per row

// Raw per-(b,chunk) column sums. Fully overwritten every launch before the
// projector reads them -> deterministic under graph replay, no zero-init.
__device__ float g_partial[BB * NCHUNK * CC];

// ---------------------------------------------------------------------------
// Kernel 1: PURE streamer (round-2 config verbatim — the 6.4 TB/s regime).
// No epilogue, no syncthreads, no fences: blocks store their sums and exit.
// 512 blocks x 288 threads; 288 x 16B = one 4608 B row -> fully coalesced;
// unroll 4 -> 4 outstanding 16B loads/thread, lean registers, one flat wave.
// ---------------------------------------------------------------------------
__global__ __launch_bounds__(C4, 4) void reduce_t_kernel(const float* __restrict__ x) {
    const int blk   = blockIdx.x;
    const int b     = blk / NCHUNK;
    const int chunk = blk % NCHUNK;
    const int tid   = threadIdx.x;

    const float4* xp = reinterpret_cast<const float4*>(x)
                     + ((size_t)b * TT + (size_t)chunk * TROWS) * C4 + tid;

    float4 acc = make_float4(0.f, 0.f, 0.f, 0.f);

    #pragma unroll 1
    for (int t = 0; t < TROWS; t += 4) {
        float4 v0 = xp[(size_t)(t + 0) * C4];
        float4 v1 = xp[(size_t)(t + 1) * C4];
        float4 v2 = xp[(size_t)(t + 2) * C4];
        float4 v3 = xp[(size_t)(t + 3) * C4];
        acc.x += (v0.x + v1.x) + (v2.x + v3.x);
        acc.y += (v0.y + v1.y) + (v2.y + v3.y);
        acc.z += (v0.z + v1.z) + (v2.z + v3.z);
        acc.w += (v0.w + v1.w) + (v2.w + v3.w);
    }

    reinterpret_cast<float4*>(g_partial)[(size_t)blk * C4 + tid] = acc;
}

// ---------------------------------------------------------------------------
// Kernel 2: per-batch collapse + projection + finish, engineered for latency:
// 32 blocks (one per batch) x 288 threads.
//   collapse: each thread owns one float4 column-group, 16 INDEPENDENT L2
//             loads (MLP 16), ordered sum -> deterministic -> smem.
//   project:  9 warps round-robin 29 outputs, float4 W rows (9 iters),
//             val[c] = s[c]/64 - 2*TT folded into the dot.
//   finish:   + T*bias, / length (int32 on device: JAX downcasts int64).
// ~206 KB L2-resident reads per block, each on its own SM: ~2-3 us total.
// ---------------------------------------------------------------------------
__global__ __launch_bounds__(C4) void project_kernel(const int*   __restrict__ length,
                                                     const float* __restrict__ W,
                                                     const float* __restrict__ bias,
                                                     float*       __restrict__ out) {
    __shared__ float s[CC];
    __shared__ float zdot[32];

    const int b   = blockIdx.x;
    const int tid = threadIdx.x;

    // Collapse 16 chunk vectors -> s (fully unrolled: 16 loads in flight).
    {
        const float4* gp4 = reinterpret_cast<const float4*>(g_partial)
                          + (size_t)b * NCHUNK * C4 + tid;
        float4 v[NCHUNK];
        #pragma unroll
        for (int ch = 0; ch < NCHUNK; ch++)
            v[ch] = gp4[(size_t)ch * C4];

        float4 r = v[0];
        #pragma unroll
        for (int ch = 1; ch < NCHUNK; ch++) {
            r.x += v[ch].x; r.y += v[ch].y; r.z += v[ch].z; r.w += v[ch].w;
        }
        reinterpret_cast<float4*>(s)[tid] = r;
    }
    __syncthreads();

    const int warp = tid >> 5;
    const int lane = tid & 31;
    const float inv64 = 1.0f / 64.0f;
    const float shift = 2.0f * (float)TT;    // 4096

    const float4* s4 = reinterpret_cast<const float4*>(s);

    for (int o = warp; o < OO; o += 9) {
        const float4* wr4 = reinterpret_cast<const float4*>(W + (size_t)o * CC);
        float dot = 0.f;
        #pragma unroll
        for (int k = 0; k < C4 / 32; k++) {      // 9 iterations
            int idx = lane + k * 32;
            float4 w = wr4[idx];
            float4 v = s4[idx];
            dot = fmaf(fmaf(v.x, inv64, -shift), w.x, dot);
            dot = fmaf(fmaf(v.y, inv64, -shift), w.y, dot);
            dot = fmaf(fmaf(v.z, inv64, -shift), w.z, dot);
            dot = fmaf(fmaf(v.w, inv64, -shift), w.w, dot);
        }
        #pragma unroll
        for (int off = 16; off; off >>= 1)
            dot += __shfl_down_sync(0xffffffffu, dot, off);
        if (lane == 0)
            zdot[o] = dot;
    }
    __syncthreads();

    if (tid < OO)
        out[(size_t)b * OO + tid] = (zdot[tid] + (float)TT * bias[tid])
                                  / (float)length[b];
}

// ---------------------------------------------------------------------------
// Inputs (metadata order): x f32 [B,T,C], length i32 [B], W f32 [O,C], b f32 [O]
// Output: f32 [B,O]
// ---------------------------------------------------------------------------
extern "C" void kernel_launch(void* const* d_in, const int* in_sizes, int n_in,
                              void* d_out, int out_size) {
    (void)in_sizes; (void)n_in; (void)out_size;
    const float* x      = (const float*)d_in[0];
    const int*   length = (const int*)d_in[1];
    const float* W      = (const float*)d_in[2];
    const float* bias   = (const float*)d_in[3];
    float*       out    = (float*)d_out;

    reduce_t_kernel<<<NBLK, C4>>>(x);
    project_kernel<<<BB, C4>>>(length, W, bias, out);
}